// round 15
// baseline (speedup 1.0000x reference)
#include <cuda_runtime.h>
#include <cuda_bf16.h>
#include <math.h>

#define B 128
#define T 32
#define S 512
#define H 1024
#define IN_DIM 1024
#define G4 4096          // 4*H
#define KREC 2048        // H (ha) + H (h)

#define SK_GATES 4
#define SK_HTIL 16
#define SK_WOUT 16
#define NSPLIT 4

// ---- output offsets (flattened tuple, fp32) ----
#define OFF_OUT   0ull
#define OFF_H     4194304ull
#define OFF_C     4325376ull
#define OFF_HA    4456448ull
#define OFF_ATTN  4587520ull
#define OFF_PATTN 6684672ull
#define OFF_P     6750208ull
#define OFF_DEHY  6754304ull
#define OFF_LOSS  6885376ull

// ---- scratch ----
__device__ float g_Xg[(size_t)B * T * G4];        // rows (b*T + t)
__device__ float g_biasg[G4];
__device__ float g_gates_part[SK_GATES * B * G4];
__device__ float g_htil_part[SK_HTIL * B * H];
__device__ float g_wout_part[SK_WOUT * B * H];
__device__ float g_Arec[B * KREC];                // fp32 ha (final output)
__device__ float g_h[B * H];
__device__ float g_c[B * H];
__device__ float g_logits[B * S];
__device__ float g_part_acc[B * NSPLIT * H];
__device__ float g_part_m[B * NSPLIT];
__device__ float g_part_l[B * NSPLIT];
__device__ int   g_cnt[B];                        // zero-init; self-resetting

// bf16 hi/lo split weights (built once in prep)
__device__ __nv_bfloat16 g_Wr_h[(size_t)G4 * KREC];
__device__ __nv_bfloat16 g_Wr_l[(size_t)G4 * KREC];
__device__ __nv_bfloat16 g_Wat_h[H * H];
__device__ __nv_bfloat16 g_Wat_l[H * H];
__device__ __nv_bfloat16 g_Wout_h[H * KREC];
__device__ __nv_bfloat16 g_Wout_l[H * KREC];
__device__ __nv_bfloat16 g_Wih_h[(size_t)G4 * IN_DIM];
__device__ __nv_bfloat16 g_Wih_l[(size_t)G4 * IN_DIM];
__device__ __nv_bfloat16 g_in_h[(size_t)B * T * IN_DIM];
__device__ __nv_bfloat16 g_in_l[(size_t)B * T * IN_DIM];
// bf16 hi/lo activations
__device__ __nv_bfloat16 g_Arec_h[B * KREC];
__device__ __nv_bfloat16 g_Arec_l[B * KREC];
__device__ __nv_bfloat16 g_Aout_h[B * KREC];
__device__ __nv_bfloat16 g_Aout_l[B * KREC];
__device__ __nv_bfloat16 g_h_h[B * H];
__device__ __nv_bfloat16 g_h_l[B * H];

__device__ __forceinline__ void split2(float x, __nv_bfloat16& hi, __nv_bfloat16& lo)
{
    hi = __float2bfloat16(x);
    lo = __float2bfloat16(x - __bfloat162float(hi));
}
__device__ __forceinline__ unsigned packbf2(float a, float b)
{
    __nv_bfloat162 t = __floats2bfloat162_rn(a, b);
    return *(unsigned*)&t;
}
__device__ __forceinline__ float lobf(float x)
{
    return x - __bfloat162float(__float2bfloat16(x));
}

// ============================================================
// Tensor-core GEMM: C = A @ W.T with bf16x3 split.
// Burst L2 prefetch of the block's full W working set at entry
// (bulk-parallel DRAM fill), then cp.async pipeline hits L2.
// ============================================================
#define SKP  40
#define TILE (128 * SKP)

__device__ __forceinline__ void ldsm4(unsigned* r, unsigned addr)
{
    asm volatile("ldmatrix.sync.aligned.m8n8.x4.shared.b16 {%0,%1,%2,%3}, [%4];"
                 : "=r"(r[0]), "=r"(r[1]), "=r"(r[2]), "=r"(r[3]) : "r"(addr));
}
__device__ __forceinline__ void mma16816(float* d, const unsigned* a, const unsigned* b)
{
    asm volatile("mma.sync.aligned.m16n8k16.row.col.f32.bf16.bf16.f32 "
                 "{%0,%1,%2,%3}, {%4,%5,%6,%7}, {%8,%9}, {%0,%1,%2,%3};"
                 : "+f"(d[0]), "+f"(d[1]), "+f"(d[2]), "+f"(d[3])
                 : "r"(a[0]), "r"(a[1]), "r"(a[2]), "r"(a[3]), "r"(b[0]), "r"(b[1]));
}
#define CP16(dst, src) \
    asm volatile("cp.async.cg.shared.global [%0], [%1], 16;" :: "r"(dst), "l"(src))
#define CP_COMMIT() asm volatile("cp.async.commit_group;")
#define CP_WAIT(n)  asm volatile("cp.async.wait_group %0;" :: "n"(n))
#define PF_L2(p) asm volatile("prefetch.global.L2 [%0];" :: "l"(p))

template <int BM, int NST>
__global__ __launch_bounds__(256, (BM == 64) ? 2 : 1)
void hgemm_tn(const __nv_bfloat16* __restrict__ Ah, const __nv_bfloat16* __restrict__ Al,
              int lda,
              const __nv_bfloat16* __restrict__ Wh, const __nv_bfloat16* __restrict__ Wl,
              int ldw,
              float* __restrict__ Cpart, int M, int N, int Kslice,
              const float* __restrict__ bias)
{
    constexpr int ATILE = BM * SKP;             // A tile elems (one component)
    constexpr int STAGE = 2 * ATILE + 2 * TILE; // elems per stage
    constexpr int MT = BM / 32;                 // m-tiles per warp

    extern __shared__ __nv_bfloat16 smem[];
    const int bn = blockIdx.x, bm = blockIdx.y, bz = blockIdx.z;
    Ah += (size_t)bm * BM * lda + (size_t)bz * Kslice;
    Al += (size_t)bm * BM * lda + (size_t)bz * Kslice;
    Wh += (size_t)bn * 128 * ldw + (size_t)bz * Kslice;
    Wl += (size_t)bn * 128 * ldw + (size_t)bz * Kslice;
    float* C = Cpart + (size_t)bz * M * N + (size_t)bm * BM * N + (size_t)bn * 128;

    const int tid = threadIdx.x;
    const int warp = tid >> 5, lane = tid & 31;
    const int wm = (warp >> 2) * (BM / 2);
    const int wn = (warp & 3) * 32;

    // ---- burst-prefetch this block's W tiles (hi & lo) into L2 ----
    {
        const int lpr = Kslice >> 6;          // 128B lines per row
        const int nl = 128 * lpr;
        for (int i = tid; i < nl; i += 256) {
            int row = i / lpr;
            int col = (i - row * lpr) << 6;   // element offset (64 bf16 = 128 B)
            PF_L2(Wh + (size_t)row * ldw + col);
            PF_L2(Wl + (size_t)row * ldw + col);
        }
    }

    const unsigned sbase = (unsigned)__cvta_generic_to_shared(smem);

    float acc[MT][4][4];
#pragma unroll
    for (int i = 0; i < MT; i++)
#pragma unroll
        for (int j = 0; j < 4; j++)
#pragma unroll
            for (int q = 0; q < 4; q++) acc[i][j][q] = 0.f;

    const int nIter = Kslice >> 5;

    auto load_stage = [&](int stage, int ko) {
        unsigned sb = sbase + (unsigned)(stage * STAGE) * 2;
#pragma unroll
        for (int i = 0; i < BM / 64; i++) {
            int idx = i * 256 + tid;
            int row = idx >> 2, ch = (idx & 3) * 8;
            unsigned doff = (unsigned)(row * SKP + ch) * 2;
            size_t ga = (size_t)row * lda + ko + ch;
            CP16(sb + doff,                          Ah + ga);
            CP16(sb + (unsigned)ATILE * 2 + doff,    Al + ga);
        }
#pragma unroll
        for (int i = 0; i < 2; i++) {
            int idx = i * 256 + tid;
            int row = idx >> 2, ch = (idx & 3) * 8;
            unsigned doff = (unsigned)(row * SKP + ch) * 2;
            size_t gw = (size_t)row * ldw + ko + ch;
            CP16(sb + (unsigned)(2 * ATILE) * 2 + doff,        Wh + gw);
            CP16(sb + (unsigned)(2 * ATILE + TILE) * 2 + doff, Wl + gw);
        }
    };

    for (int s = 0; s < NST - 1 && s < nIter; s++) {
        load_stage(s, s * 32);
        CP_COMMIT();
    }

    const int rA = lane & 15;
    const int kA = (lane >> 4) * 8;
    const int rB = (lane & 7) + ((lane & 16) ? 8 : 0);
    const int kB = (lane & 8);

    int sIdx = 0, tIdx = NST - 1;
    for (int it = 0; it < nIter; it++) {
        if (it + NST - 1 <= nIter) { CP_WAIT(NST - 2); } else { CP_WAIT(0); }
        __syncthreads();

        unsigned base = sbase + (unsigned)(sIdx * STAGE) * 2;
#pragma unroll
        for (int k16 = 0; k16 < 32; k16 += 16) {
            unsigned ah[MT][4], al[MT][4], bh[4][2], bl[4][2];
#pragma unroll
            for (int mt = 0; mt < MT; mt++) {
                unsigned ad = base + (unsigned)((wm + mt * 16 + rA) * SKP + k16 + kA) * 2;
                ldsm4(ah[mt], ad);
                ldsm4(al[mt], ad + (unsigned)ATILE * 2);
            }
#pragma unroll
            for (int np = 0; np < 2; np++) {
                unsigned bd = base + (unsigned)(2 * ATILE) * 2 +
                              (unsigned)((wn + np * 16 + rB) * SKP + k16 + kB) * 2;
                unsigned r[4];
                ldsm4(r, bd);
                bh[np * 2][0] = r[0]; bh[np * 2][1] = r[1];
                bh[np * 2 + 1][0] = r[2]; bh[np * 2 + 1][1] = r[3];
                ldsm4(r, bd + (unsigned)TILE * 2);
                bl[np * 2][0] = r[0]; bl[np * 2][1] = r[1];
                bl[np * 2 + 1][0] = r[2]; bl[np * 2 + 1][1] = r[3];
            }
#pragma unroll
            for (int mt = 0; mt < MT; mt++)
#pragma unroll
                for (int nt = 0; nt < 4; nt++) {
                    mma16816(acc[mt][nt], ah[mt], bh[nt]);
                    mma16816(acc[mt][nt], al[mt], bh[nt]);
                    mma16816(acc[mt][nt], ah[mt], bl[nt]);
                }
        }
        if (it + NST - 1 < nIter) {
            load_stage(tIdx, (it + NST - 1) * 32);
            CP_COMMIT();
        }
        sIdx = (sIdx + 1 == NST) ? 0 : sIdx + 1;
        tIdx = (tIdx + 1 == NST) ? 0 : tIdx + 1;
    }

    const int er = lane >> 2;
    const int ec = (lane & 3) * 2;
#pragma unroll
    for (int mt = 0; mt < MT; mt++)
#pragma unroll
        for (int nt = 0; nt < 4; nt++) {
            int r0 = wm + mt * 16 + er;
            int c0 = wn + nt * 8 + ec;
            float b0 = 0.f, b1 = 0.f;
            if (bias != nullptr) {
                b0 = bias[bn * 128 + c0];
                b1 = bias[bn * 128 + c0 + 1];
            }
            float* p0 = C + (size_t)r0 * N + c0;
            float* p1 = C + (size_t)(r0 + 8) * N + c0;
            p0[0] = acc[mt][nt][0] + b0;
            p0[1] = acc[mt][nt][1] + b1;
            p1[0] = acc[mt][nt][2] + b0;
            p1[1] = acc[mt][nt][3] + b1;
        }
}

#define SMEM64  (3 * (2 * 64 * SKP + 2 * TILE) * 2)
#define SMEM128 (4 * (2 * 128 * SKP + 2 * TILE) * 2)

// ============================================================
// Setup kernels
// ============================================================
__global__ void prep_kernel(const float* __restrict__ W_ih, const float* __restrict__ W_hh,
                            const float* __restrict__ b_ih, const float* __restrict__ b_hh,
                            const float* __restrict__ W_attn, const float* __restrict__ W_out,
                            const float* __restrict__ input_)
{
    size_t stride = (size_t)gridDim.x * blockDim.x;
    size_t start = (size_t)blockIdx.x * blockDim.x + threadIdx.x;
    for (size_t idx = start; idx < (size_t)G4 * KREC; idx += stride) {
        int n = (int)(idx >> 11);
        int k = (int)(idx & 2047);
        float v = (k < H) ? W_ih[(size_t)n * KREC + IN_DIM + k]
                          : W_hh[(size_t)n * H + (k - H)];
        split2(v, g_Wr_h[idx], g_Wr_l[idx]);
    }
    for (size_t idx = start; idx < (size_t)H * H; idx += stride) {
        int n = (int)(idx >> 10), k = (int)(idx & 1023);
        split2(W_attn[(size_t)k * H + n], g_Wat_h[idx], g_Wat_l[idx]);
    }
    for (size_t idx = start; idx < (size_t)H * KREC; idx += stride)
        split2(W_out[idx], g_Wout_h[idx], g_Wout_l[idx]);
    for (size_t idx = start; idx < (size_t)G4 * IN_DIM; idx += stride) {
        int n = (int)(idx >> 10), k = (int)(idx & 1023);
        split2(W_ih[(size_t)n * KREC + k], g_Wih_h[idx], g_Wih_l[idx]);
    }
    for (size_t idx = start; idx < (size_t)B * T * IN_DIM; idx += stride)
        split2(input_[idx], g_in_h[idx], g_in_l[idx]);
    for (size_t idx = start; idx < (size_t)G4; idx += stride)
        g_biasg[idx] = b_ih[idx] + b_hh[idx];
}

__global__ void init_kernel(const float* __restrict__ hh, const float* __restrict__ hc,
                            const float* __restrict__ ha)
{
    int idx = blockIdx.x * blockDim.x + threadIdx.x;
    if (idx < B * H) {
        int b = idx >> 10, n = idx & 1023;
        g_h[idx] = hh[idx];
        g_c[idx] = hc[idx];
        split2(ha[idx], g_Arec_h[b * KREC + n], g_Arec_l[b * KREC + n]);
        split2(hh[idx], g_Arec_h[b * KREC + H + n], g_Arec_l[b * KREC + H + n]);
        if (idx < B) g_cnt[idx] = 0;
    }
}

// ============================================================
// LSTM cell (float4): reduce gate partials + Xg, update h/c
// ============================================================
__global__ void lstm_step(int t)
{
    int v = blockIdx.x * blockDim.x + threadIdx.x;   // B*H/4
    int b = v >> 8;
    int n4 = (v & 255) * 4;
    size_t row = ((size_t)b * T + t) * G4;
    float4 gi = __ldcs((const float4*)&g_Xg[row + n4]);
    float4 gf = __ldcs((const float4*)&g_Xg[row + H + n4]);
    float4 gg = __ldcs((const float4*)&g_Xg[row + 2 * H + n4]);
    float4 go = __ldcs((const float4*)&g_Xg[row + 3 * H + n4]);
#pragma unroll
    for (int p = 0; p < SK_GATES; p++) {
        const float* gp = g_gates_part + (size_t)p * B * G4 + (size_t)b * G4;
        float4 a = __ldcs((const float4*)&gp[n4]);
        float4 c = __ldcs((const float4*)&gp[H + n4]);
        float4 d = __ldcs((const float4*)&gp[2 * H + n4]);
        float4 e = __ldcs((const float4*)&gp[3 * H + n4]);
        gi.x += a.x; gi.y += a.y; gi.z += a.z; gi.w += a.w;
        gf.x += c.x; gf.y += c.y; gf.z += c.z; gf.w += c.w;
        gg.x += d.x; gg.y += d.y; gg.z += d.z; gg.w += d.w;
        go.x += e.x; go.y += e.y; go.z += e.z; go.w += e.w;
    }
    int idx = b * H + n4;
    float4 cold = *(const float4*)&g_c[idx];
    float hn[4], cn[4];
    float gia[4] = {gi.x, gi.y, gi.z, gi.w};
    float gfa[4] = {gf.x, gf.y, gf.z, gf.w};
    float gga[4] = {gg.x, gg.y, gg.z, gg.w};
    float goa[4] = {go.x, go.y, go.z, go.w};
    float ca[4] = {cold.x, cold.y, cold.z, cold.w};
#pragma unroll
    for (int j = 0; j < 4; j++) {
        float i_ = 1.f / (1.f + expf(-gia[j]));
        float f_ = 1.f / (1.f + expf(-gfa[j]));
        float g_ = tanhf(gga[j]);
        float o_ = 1.f / (1.f + expf(-goa[j]));
        cn[j] = f_ * ca[j] + i_ * g_;
        hn[j] = o_ * tanhf(cn[j]);
    }
    *(float4*)&g_c[idx] = make_float4(cn[0], cn[1], cn[2], cn[3]);
    *(float4*)&g_h[idx] = make_float4(hn[0], hn[1], hn[2], hn[3]);
    uint2 hiP = make_uint2(packbf2(hn[0], hn[1]), packbf2(hn[2], hn[3]));
    uint2 loP = make_uint2(packbf2(lobf(hn[0]), lobf(hn[1])),
                           packbf2(lobf(hn[2]), lobf(hn[3])));
    *(uint2*)&g_h_h[idx] = hiP;                       *(uint2*)&g_h_l[idx] = loP;
    *(uint2*)&g_Arec_h[b * KREC + H + n4] = hiP;      *(uint2*)&g_Arec_l[b * KREC + H + n4] = loP;
    *(uint2*)&g_Aout_h[b * KREC + H + n4] = hiP;      *(uint2*)&g_Aout_l[b * KREC + H + n4] = loP;
}

// ============================================================
// Flash attention split + fused last-block combine/attn/p_gen.
// ============================================================
__global__ __launch_bounds__(256)
void flash_step(int t, const float* __restrict__ enc,
                const float* __restrict__ input_, const float* __restrict__ W_pt,
                const float* __restrict__ b_pt, float* __restrict__ out)
{
    int b = blockIdx.x, sp = blockIdx.y;
    __shared__ float htil[H];
    __shared__ float accS[8][1024];
    __shared__ float wm[8], wl[8], wf[8];
    __shared__ float fP[NSPLIT];
    __shared__ float sM, sL;
    __shared__ int   sLast;
    int tid = threadIdx.x;

    for (int j = tid * 4; j < H; j += 1024) {
        float4 s = make_float4(0.f, 0.f, 0.f, 0.f);
#pragma unroll
        for (int p = 0; p < SK_HTIL; p++) {
            float4 a = __ldcs((const float4*)&g_htil_part[(size_t)p * B * H + b * H + j]);
            s.x += a.x; s.y += a.y; s.z += a.z; s.w += a.w;
        }
        *(float4*)&htil[j] = s;
    }
    __syncthreads();

    int warp = tid >> 5, lane = tid & 31;
    float m = -1e30f, l = 0.f;
    float4 acc[8];
#pragma unroll
    for (int i = 0; i < 8; i++) acc[i] = make_float4(0.f, 0.f, 0.f, 0.f);

    float4 ht[8];
#pragma unroll
    for (int i = 0; i < 8; i++) ht[i] = *(const float4*)&htil[i * 128 + lane * 4];

    const float* encb = enc + (size_t)b * S * H;
    int s0 = sp * 128 + warp * 16;
    for (int si = 0; si < 16; si++) {
        int s = s0 + si;
        const float4* er = (const float4*)(encb + (size_t)s * H) + lane;
        float4 v[8];
#pragma unroll
        for (int i = 0; i < 8; i++) v[i] = __ldcs(er + i * 32);
        float d = 0.f;
#pragma unroll
        for (int i = 0; i < 8; i++)
            d += v[i].x * ht[i].x + v[i].y * ht[i].y + v[i].z * ht[i].z + v[i].w * ht[i].w;
#pragma unroll
        for (int off = 16; off > 0; off >>= 1) d += __shfl_xor_sync(0xffffffffu, d, off);
        if (lane == 0) g_logits[b * S + s] = d;
        float mn = fmaxf(m, d);
        float sc = __expf(m - mn);
        float w  = __expf(d - mn);
        l = l * sc + w;
#pragma unroll
        for (int i = 0; i < 8; i++) {
            acc[i].x = acc[i].x * sc + w * v[i].x;
            acc[i].y = acc[i].y * sc + w * v[i].y;
            acc[i].z = acc[i].z * sc + w * v[i].z;
            acc[i].w = acc[i].w * sc + w * v[i].w;
        }
        m = mn;
    }
#pragma unroll
    for (int i = 0; i < 8; i++) *(float4*)&accS[warp][i * 128 + lane * 4] = acc[i];
    if (lane == 0) { wm[warp] = m; wl[warp] = l; }
    __syncthreads();
    if (tid == 0) {
        float M = -1e30f;
        for (int w0 = 0; w0 < 8; w0++) M = fmaxf(M, wm[w0]);
        float L = 0.f;
        for (int w0 = 0; w0 < 8; w0++) { float f = __expf(wm[w0] - M); wf[w0] = f; L += wl[w0] * f; }
        g_part_m[b * NSPLIT + sp] = M;
        g_part_l[b * NSPLIT + sp] = L;
    }
    __syncthreads();
    for (int j = tid; j < H; j += 256) {
        float s = 0.f;
#pragma unroll
        for (int w0 = 0; w0 < 8; w0++) s += accS[w0][j] * wf[w0];
        g_part_acc[((size_t)b * NSPLIT + sp) * H + j] = s;
    }

    __threadfence();
    __syncthreads();
    if (tid == 0) {
        int old = atomicAdd(&g_cnt[b], 1);
        sLast = (old == NSPLIT - 1);
        if (sLast) { g_cnt[b] = 0; __threadfence(); }
    }
    __syncthreads();
    if (!sLast) return;

    if (tid == 0) {
        float M = -1e30f;
        for (int p = 0; p < NSPLIT; p++) M = fmaxf(M, g_part_m[b * NSPLIT + p]);
        float L = 0.f;
        for (int p = 0; p < NSPLIT; p++) {
            float f = __expf(g_part_m[b * NSPLIT + p] - M);
            fP[p] = f;
            L += g_part_l[b * NSPLIT + p] * f;
        }
        sM = M; sL = L;
    }
    __syncthreads();
    float invL = 1.f / sL;
    for (int j = tid; j < H; j += 256) {
        float ce = 0.f;
#pragma unroll
        for (int p = 0; p < NSPLIT; p++)
            ce += __ldcs(&g_part_acc[((size_t)b * NSPLIT + p) * H + j]) * fP[p];
        float v = ce * invL;
        htil[j] = v;
        split2(v, g_Aout_h[b * KREC + j], g_Aout_l[b * KREC + j]);
    }
    float M = sM;
    for (int s = tid; s < S; s += 256)
        out[OFF_ATTN + (size_t)t * B * S + (size_t)b * S + s] =
            __expf(__ldcs(&g_logits[b * S + s]) - M) * invL;
    __syncthreads();

    const float* xk = input_ + ((size_t)b * T + t) * IN_DIM;
    float s = 0.f;
    for (int k = tid; k < IN_DIM; k += 256) s += W_pt[k] * xk[k];
    for (int k = tid; k < H; k += 256)      s += W_pt[IN_DIM + k] * g_h[b * H + k];
    for (int k = tid; k < H; k += 256)      s += W_pt[IN_DIM + H + k] * htil[k];
    float* red = &accS[0][0];
    red[tid] = s;
    __syncthreads();
    for (int st = 128; st > 0; st >>= 1) {
        if (tid < st) red[tid] += red[tid + st];
        __syncthreads();
    }
    if (tid == 0) {
        float p = 1.f / (1.f + expf(-(red[0] + b_pt[0])));
        out[OFF_P + (size_t)b * T + t] = p;
    }
}

// ============================================================
// ha (float4): reduce wout partials + b_out; write output_/Arec
// ============================================================
__global__ void haepi_step(int t, float* __restrict__ out, const float* __restrict__ b_out)
{
    int v = blockIdx.x * blockDim.x + threadIdx.x;   // B*H/4
    int b = v >> 8;
    int n4 = (v & 255) * 4;
    int idx = b * H + n4;
    float4 s = *(const float4*)&b_out[n4];
#pragma unroll
    for (int p = 0; p < SK_WOUT; p++) {
        float4 a = __ldcs((const float4*)&g_wout_part[(size_t)p * B * H + idx]);
        s.x += a.x; s.y += a.y; s.z += a.z; s.w += a.w;
    }
    *(float4*)&g_Arec[b * KREC + n4] = s;
    uint2 hiP = make_uint2(packbf2(s.x, s.y), packbf2(s.z, s.w));
    uint2 loP = make_uint2(packbf2(lobf(s.x), lobf(s.y)),
                           packbf2(lobf(s.z), lobf(s.w)));
    *(uint2*)&g_Arec_h[b * KREC + n4] = hiP;
    *(uint2*)&g_Arec_l[b * KREC + n4] = loP;
    *(float4*)&out[OFF_OUT + ((size_t)b * T + t) * H + n4] = s;
}

__global__ void final_kernel(const float* __restrict__ past_attn_in,
                             const float* __restrict__ past_dehy_in,
                             float* __restrict__ out)
{
    int idx = blockIdx.x * blockDim.x + threadIdx.x;
    if (idx < B * H) {
        out[OFF_H + idx] = g_h[idx];
        out[OFF_C + idx] = g_c[idx];
        int b = idx >> 10, n = idx & 1023;
        out[OFF_HA + idx] = g_Arec[b * KREC + n];
        out[OFF_DEHY + idx] = past_dehy_in[idx];
    }
    if (idx < B * S) out[OFF_PATTN + idx] = past_attn_in[idx];
    if (idx == 0) out[OFF_LOSS] = 0.f;
}

// ============================================================
extern "C" void kernel_launch(void* const* d_in, const int* in_sizes, int n_in,
                              void* d_out, int out_size)
{
    int base = (in_sizes[0] == 1) ? 1 : 0;
    const float* input_    = (const float*)d_in[base + 0];
    const float* hidden_h  = (const float*)d_in[base + 1];
    const float* hidden_c  = (const float*)d_in[base + 2];
    const float* h_attn    = (const float*)d_in[base + 3];
    const float* enc       = (const float*)d_in[base + 4];
    const float* past_attn = (const float*)d_in[base + 5];
    const float* past_dehy = (const float*)d_in[base + 7];
    const float* W_ih  = (const float*)d_in[base + 8];
    const float* b_ih  = (const float*)d_in[base + 9];
    const float* W_hh  = (const float*)d_in[base + 10];
    const float* b_hh  = (const float*)d_in[base + 11];
    const float* W_attn= (const float*)d_in[base + 12];
    const float* W_out = (const float*)d_in[base + 13];
    const float* b_out = (const float*)d_in[base + 14];
    const float* W_pt  = (const float*)d_in[base + 15];
    const float* b_pt  = (const float*)d_in[base + 16];
    float* out = (float*)d_out;

    float *pXg, *pbg, *pGates, *pHtil, *pWoutp;
    __nv_bfloat16 *pWrh, *pWrl, *pWath, *pWatl, *pWouth, *pWoutl, *pWihh, *pWihl;
    __nv_bfloat16 *pInh, *pInl, *pArech, *pArecl, *pAouth, *pAoutl, *pHh, *pHl;
    cudaGetSymbolAddress((void**)&pXg,    g_Xg);
    cudaGetSymbolAddress((void**)&pbg,    g_biasg);
    cudaGetSymbolAddress((void**)&pGates, g_gates_part);
    cudaGetSymbolAddress((void**)&pHtil,  g_htil_part);
    cudaGetSymbolAddress((void**)&pWoutp, g_wout_part);
    cudaGetSymbolAddress((void**)&pWrh,   g_Wr_h);
    cudaGetSymbolAddress((void**)&pWrl,   g_Wr_l);
    cudaGetSymbolAddress((void**)&pWath,  g_Wat_h);
    cudaGetSymbolAddress((void**)&pWatl,  g_Wat_l);
    cudaGetSymbolAddress((void**)&pWouth, g_Wout_h);
    cudaGetSymbolAddress((void**)&pWoutl, g_Wout_l);
    cudaGetSymbolAddress((void**)&pWihh,  g_Wih_h);
    cudaGetSymbolAddress((void**)&pWihl,  g_Wih_l);
    cudaGetSymbolAddress((void**)&pInh,   g_in_h);
    cudaGetSymbolAddress((void**)&pInl,   g_in_l);
    cudaGetSymbolAddress((void**)&pArech, g_Arec_h);
    cudaGetSymbolAddress((void**)&pArecl, g_Arec_l);
    cudaGetSymbolAddress((void**)&pAouth, g_Aout_h);
    cudaGetSymbolAddress((void**)&pAoutl, g_Aout_l);
    cudaGetSymbolAddress((void**)&pHh,    g_h_h);
    cudaGetSymbolAddress((void**)&pHl,    g_h_l);

    static bool attr_set = false;
    if (!attr_set) {
        cudaFuncSetAttribute((const void*)hgemm_tn<128, 4>,
                             cudaFuncAttributeMaxDynamicSharedMemorySize, SMEM128);
        cudaFuncSetAttribute((const void*)hgemm_tn<64, 3>,
                             cudaFuncAttributeMaxDynamicSharedMemorySize, SMEM64);
        attr_set = true;
    }

    prep_kernel<<<2048, 256>>>(W_ih, W_hh, b_ih, b_hh, W_attn, W_out, input_);
    init_kernel<<<(B * H + 255) / 256, 256>>>(hidden_h, hidden_c, h_attn);

    // Xg = input_ @ W_ih[:, :IN].T + (b_ih + b_hh)
    hgemm_tn<128, 4><<<dim3(G4 / 128, (B * T) / 128, 1), 256, SMEM128>>>(
        pInh, pInl, IN_DIM, pWihh, pWihl, IN_DIM, pXg, B * T, G4, IN_DIM, pbg);

    for (int t = 0; t < T; t++) {
        // gates partial: [ha, h] @ [W_ih[:,IN:], W_hh].T  (BM=64, 2 blk/SM)
        hgemm_tn<64, 3><<<dim3(G4 / 128, 2, SK_GATES), 256, SMEM64>>>(
            pArech, pArecl, KREC, pWrh, pWrl, KREC, pGates, B, G4,
            KREC / SK_GATES, nullptr);
        lstm_step<<<(B * H / 4) / 256, 256>>>(t);
        // h~ = h @ W_attn
        hgemm_tn<64, 3><<<dim3(H / 128, 2, SK_HTIL), 256, SMEM64>>>(
            pHh, pHl, H, pWath, pWatl, H, pHtil, B, H, H / SK_HTIL, nullptr);
        flash_step<<<dim3(B, NSPLIT), 256>>>(t, enc, input_, W_pt, b_pt, out);
        // ha partial: [c_enc, h] @ W_out.T
        hgemm_tn<64, 3><<<dim3(H / 128, 2, SK_WOUT), 256, SMEM64>>>(
            pAouth, pAoutl, KREC, pWouth, pWoutl, KREC, pWoutp, B, H,
            KREC / SK_WOUT, nullptr);
        haepi_step<<<(B * H / 4) / 256, 256>>>(t, out, b_out);
    }
    final_kernel<<<(B * H + 255) / 256, 256>>>(past_attn, past_dehy, out);
}

// round 16
// speedup vs baseline: 1.0156x; 1.0156x over previous
#include <cuda_runtime.h>
#include <cuda_bf16.h>
#include <math.h>

#define B 128
#define T 32
#define S 512
#define H 1024
#define IN_DIM 1024
#define G4 4096          // 4*H
#define KREC 2048        // H (ha) + H (h)

#define SK_GATES 4
#define SK_HTIL 16
#define SK_WOUT 16
#define NSPLIT 4

// ---- output offsets (flattened tuple, fp32) ----
#define OFF_OUT   0ull
#define OFF_H     4194304ull
#define OFF_C     4325376ull
#define OFF_HA    4456448ull
#define OFF_ATTN  4587520ull
#define OFF_PATTN 6684672ull
#define OFF_P     6750208ull
#define OFF_DEHY  6754304ull
#define OFF_LOSS  6885376ull

// ---- scratch ----
__device__ float g_Xg[(size_t)B * T * G4];        // rows (b*T + t)
__device__ float g_biasg[G4];
__device__ float g_gates_part[SK_GATES * B * G4];
__device__ float g_htil_part[SK_HTIL * B * H];
__device__ float g_wout_part[SK_WOUT * B * H];
__device__ float g_Arec[B * KREC];                // fp32 ha (final output)
__device__ float g_h[B * H];
__device__ float g_c[B * H];
__device__ float g_logits[B * S];
__device__ float g_part_acc[B * NSPLIT * H];
__device__ float g_part_m[B * NSPLIT];
__device__ float g_part_l[B * NSPLIT];
__device__ int   g_cnt[B];                        // zero-init; self-resetting

// bf16 hi/lo split weights (built once in prep)
__device__ __nv_bfloat16 g_Wr_h[(size_t)G4 * KREC];
__device__ __nv_bfloat16 g_Wr_l[(size_t)G4 * KREC];
__device__ __nv_bfloat16 g_Wat_h[H * H];
__device__ __nv_bfloat16 g_Wat_l[H * H];
__device__ __nv_bfloat16 g_Wout_h[H * KREC];
__device__ __nv_bfloat16 g_Wout_l[H * KREC];
__device__ __nv_bfloat16 g_Wih_h[(size_t)G4 * IN_DIM];
__device__ __nv_bfloat16 g_Wih_l[(size_t)G4 * IN_DIM];
__device__ __nv_bfloat16 g_in_h[(size_t)B * T * IN_DIM];
__device__ __nv_bfloat16 g_in_l[(size_t)B * T * IN_DIM];
// bf16 hi/lo activations
__device__ __nv_bfloat16 g_Arec_h[B * KREC];
__device__ __nv_bfloat16 g_Arec_l[B * KREC];
__device__ __nv_bfloat16 g_Aout_h[B * KREC];
__device__ __nv_bfloat16 g_Aout_l[B * KREC];
__device__ __nv_bfloat16 g_h_h[B * H];
__device__ __nv_bfloat16 g_h_l[B * H];

__device__ __forceinline__ void split2(float x, __nv_bfloat16& hi, __nv_bfloat16& lo)
{
    hi = __float2bfloat16(x);
    lo = __float2bfloat16(x - __bfloat162float(hi));
}
__device__ __forceinline__ unsigned packbf2(float a, float b)
{
    __nv_bfloat162 t = __floats2bfloat162_rn(a, b);
    return *(unsigned*)&t;
}
__device__ __forceinline__ float lobf(float x)
{
    return x - __bfloat162float(__float2bfloat16(x));
}

// ============================================================
// Tensor-core GEMM: C = A @ W.T with bf16x3 split.
// BM=64 tiles, NST=3 stages, 2 blocks/SM (16 warps/SM).
// ============================================================
#define SKP  40
#define TILE (128 * SKP)

__device__ __forceinline__ void ldsm4(unsigned* r, unsigned addr)
{
    asm volatile("ldmatrix.sync.aligned.m8n8.x4.shared.b16 {%0,%1,%2,%3}, [%4];"
                 : "=r"(r[0]), "=r"(r[1]), "=r"(r[2]), "=r"(r[3]) : "r"(addr));
}
__device__ __forceinline__ void mma16816(float* d, const unsigned* a, const unsigned* b)
{
    asm volatile("mma.sync.aligned.m16n8k16.row.col.f32.bf16.bf16.f32 "
                 "{%0,%1,%2,%3}, {%4,%5,%6,%7}, {%8,%9}, {%0,%1,%2,%3};"
                 : "+f"(d[0]), "+f"(d[1]), "+f"(d[2]), "+f"(d[3])
                 : "r"(a[0]), "r"(a[1]), "r"(a[2]), "r"(a[3]), "r"(b[0]), "r"(b[1]));
}
#define CP16(dst, src) \
    asm volatile("cp.async.cg.shared.global [%0], [%1], 16;" :: "r"(dst), "l"(src))
#define CP_COMMIT() asm volatile("cp.async.commit_group;")
#define CP_WAIT(n)  asm volatile("cp.async.wait_group %0;" :: "n"(n))

template <int BM, int NST>
__global__ __launch_bounds__(256, (BM == 64) ? 2 : 1)
void hgemm_tn(const __nv_bfloat16* __restrict__ Ah, const __nv_bfloat16* __restrict__ Al,
              int lda,
              const __nv_bfloat16* __restrict__ Wh, const __nv_bfloat16* __restrict__ Wl,
              int ldw,
              float* __restrict__ Cpart, int M, int N, int Kslice,
              const float* __restrict__ bias)
{
    constexpr int ATILE = BM * SKP;             // A tile elems (one component)
    constexpr int STAGE = 2 * ATILE + 2 * TILE; // elems per stage
    constexpr int MT = BM / 32;                 // m-tiles per warp

    extern __shared__ __nv_bfloat16 smem[];
    const int bn = blockIdx.x, bm = blockIdx.y, bz = blockIdx.z;
    Ah += (size_t)bm * BM * lda + (size_t)bz * Kslice;
    Al += (size_t)bm * BM * lda + (size_t)bz * Kslice;
    Wh += (size_t)bn * 128 * ldw + (size_t)bz * Kslice;
    Wl += (size_t)bn * 128 * ldw + (size_t)bz * Kslice;
    float* C = Cpart + (size_t)bz * M * N + (size_t)bm * BM * N + (size_t)bn * 128;

    const int tid = threadIdx.x;
    const int warp = tid >> 5, lane = tid & 31;
    const int wm = (warp >> 2) * (BM / 2);
    const int wn = (warp & 3) * 32;

    const unsigned sbase = (unsigned)__cvta_generic_to_shared(smem);

    float acc[MT][4][4];
#pragma unroll
    for (int i = 0; i < MT; i++)
#pragma unroll
        for (int j = 0; j < 4; j++)
#pragma unroll
            for (int q = 0; q < 4; q++) acc[i][j][q] = 0.f;

    const int nIter = Kslice >> 5;

    auto load_stage = [&](int stage, int ko) {
        unsigned sb = sbase + (unsigned)(stage * STAGE) * 2;
#pragma unroll
        for (int i = 0; i < BM / 64; i++) {
            int idx = i * 256 + tid;
            int row = idx >> 2, ch = (idx & 3) * 8;
            unsigned doff = (unsigned)(row * SKP + ch) * 2;
            size_t ga = (size_t)row * lda + ko + ch;
            CP16(sb + doff,                          Ah + ga);
            CP16(sb + (unsigned)ATILE * 2 + doff,    Al + ga);
        }
#pragma unroll
        for (int i = 0; i < 2; i++) {
            int idx = i * 256 + tid;
            int row = idx >> 2, ch = (idx & 3) * 8;
            unsigned doff = (unsigned)(row * SKP + ch) * 2;
            size_t gw = (size_t)row * ldw + ko + ch;
            CP16(sb + (unsigned)(2 * ATILE) * 2 + doff,        Wh + gw);
            CP16(sb + (unsigned)(2 * ATILE + TILE) * 2 + doff, Wl + gw);
        }
    };

    for (int s = 0; s < NST - 1 && s < nIter; s++) {
        load_stage(s, s * 32);
        CP_COMMIT();
    }

    const int rA = lane & 15;
    const int kA = (lane >> 4) * 8;
    const int rB = (lane & 7) + ((lane & 16) ? 8 : 0);
    const int kB = (lane & 8);

    int sIdx = 0, tIdx = NST - 1;
    for (int it = 0; it < nIter; it++) {
        if (it + NST - 1 <= nIter) { CP_WAIT(NST - 2); } else { CP_WAIT(0); }
        __syncthreads();

        unsigned base = sbase + (unsigned)(sIdx * STAGE) * 2;
#pragma unroll
        for (int k16 = 0; k16 < 32; k16 += 16) {
            unsigned ah[MT][4], al[MT][4], bh[4][2], bl[4][2];
#pragma unroll
            for (int mt = 0; mt < MT; mt++) {
                unsigned ad = base + (unsigned)((wm + mt * 16 + rA) * SKP + k16 + kA) * 2;
                ldsm4(ah[mt], ad);
                ldsm4(al[mt], ad + (unsigned)ATILE * 2);
            }
#pragma unroll
            for (int np = 0; np < 2; np++) {
                unsigned bd = base + (unsigned)(2 * ATILE) * 2 +
                              (unsigned)((wn + np * 16 + rB) * SKP + k16 + kB) * 2;
                unsigned r[4];
                ldsm4(r, bd);
                bh[np * 2][0] = r[0]; bh[np * 2][1] = r[1];
                bh[np * 2 + 1][0] = r[2]; bh[np * 2 + 1][1] = r[3];
                ldsm4(r, bd + (unsigned)TILE * 2);
                bl[np * 2][0] = r[0]; bl[np * 2][1] = r[1];
                bl[np * 2 + 1][0] = r[2]; bl[np * 2 + 1][1] = r[3];
            }
#pragma unroll
            for (int mt = 0; mt < MT; mt++)
#pragma unroll
                for (int nt = 0; nt < 4; nt++) {
                    mma16816(acc[mt][nt], ah[mt], bh[nt]);
                    mma16816(acc[mt][nt], al[mt], bh[nt]);
                    mma16816(acc[mt][nt], ah[mt], bl[nt]);
                }
        }
        if (it + NST - 1 < nIter) {
            load_stage(tIdx, (it + NST - 1) * 32);
            CP_COMMIT();
        }
        sIdx = (sIdx + 1 == NST) ? 0 : sIdx + 1;
        tIdx = (tIdx + 1 == NST) ? 0 : tIdx + 1;
    }

    const int er = lane >> 2;
    const int ec = (lane & 3) * 2;
#pragma unroll
    for (int mt = 0; mt < MT; mt++)
#pragma unroll
        for (int nt = 0; nt < 4; nt++) {
            int r0 = wm + mt * 16 + er;
            int c0 = wn + nt * 8 + ec;
            float b0 = 0.f, b1 = 0.f;
            if (bias != nullptr) {
                b0 = bias[bn * 128 + c0];
                b1 = bias[bn * 128 + c0 + 1];
            }
            float* p0 = C + (size_t)r0 * N + c0;
            float* p1 = C + (size_t)(r0 + 8) * N + c0;
            p0[0] = acc[mt][nt][0] + b0;
            p0[1] = acc[mt][nt][1] + b1;
            p1[0] = acc[mt][nt][2] + b0;
            p1[1] = acc[mt][nt][3] + b1;
        }
}

#define SMEM64  (3 * (2 * 64 * SKP + 2 * TILE) * 2)

// ============================================================
// Setup kernels
// ============================================================
__global__ void prep_kernel(const float* __restrict__ W_ih, const float* __restrict__ W_hh,
                            const float* __restrict__ b_ih, const float* __restrict__ b_hh,
                            const float* __restrict__ W_attn, const float* __restrict__ W_out,
                            const float* __restrict__ input_)
{
    size_t stride = (size_t)gridDim.x * blockDim.x;
    size_t start = (size_t)blockIdx.x * blockDim.x + threadIdx.x;
    for (size_t idx = start; idx < (size_t)G4 * KREC; idx += stride) {
        int n = (int)(idx >> 11);
        int k = (int)(idx & 2047);
        float v = (k < H) ? W_ih[(size_t)n * KREC + IN_DIM + k]
                          : W_hh[(size_t)n * H + (k - H)];
        split2(v, g_Wr_h[idx], g_Wr_l[idx]);
    }
    for (size_t idx = start; idx < (size_t)H * H; idx += stride) {
        int n = (int)(idx >> 10), k = (int)(idx & 1023);
        split2(W_attn[(size_t)k * H + n], g_Wat_h[idx], g_Wat_l[idx]);
    }
    for (size_t idx = start; idx < (size_t)H * KREC; idx += stride)
        split2(W_out[idx], g_Wout_h[idx], g_Wout_l[idx]);
    for (size_t idx = start; idx < (size_t)G4 * IN_DIM; idx += stride) {
        int n = (int)(idx >> 10), k = (int)(idx & 1023);
        split2(W_ih[(size_t)n * KREC + k], g_Wih_h[idx], g_Wih_l[idx]);
    }
    for (size_t idx = start; idx < (size_t)B * T * IN_DIM; idx += stride)
        split2(input_[idx], g_in_h[idx], g_in_l[idx]);
    for (size_t idx = start; idx < (size_t)G4; idx += stride)
        g_biasg[idx] = b_ih[idx] + b_hh[idx];
}

__global__ void init_kernel(const float* __restrict__ hh, const float* __restrict__ hc,
                            const float* __restrict__ ha)
{
    int idx = blockIdx.x * blockDim.x + threadIdx.x;
    if (idx < B * H) {
        int b = idx >> 10, n = idx & 1023;
        g_h[idx] = hh[idx];
        g_c[idx] = hc[idx];
        split2(ha[idx], g_Arec_h[b * KREC + n], g_Arec_l[b * KREC + n]);
        split2(hh[idx], g_Arec_h[b * KREC + H + n], g_Arec_l[b * KREC + H + n]);
        if (idx < B) g_cnt[idx] = 0;
    }
}

// ============================================================
// LSTM cell (float4): reduce gate partials + Xg, update h/c
// ============================================================
__global__ void lstm_step(int t)
{
    int v = blockIdx.x * blockDim.x + threadIdx.x;   // B*H/4
    int b = v >> 8;
    int n4 = (v & 255) * 4;
    size_t row = ((size_t)b * T + t) * G4;
    float4 gi = __ldcs((const float4*)&g_Xg[row + n4]);
    float4 gf = __ldcs((const float4*)&g_Xg[row + H + n4]);
    float4 gg = __ldcs((const float4*)&g_Xg[row + 2 * H + n4]);
    float4 go = __ldcs((const float4*)&g_Xg[row + 3 * H + n4]);
#pragma unroll
    for (int p = 0; p < SK_GATES; p++) {
        const float* gp = g_gates_part + (size_t)p * B * G4 + (size_t)b * G4;
        float4 a = __ldcs((const float4*)&gp[n4]);
        float4 c = __ldcs((const float4*)&gp[H + n4]);
        float4 d = __ldcs((const float4*)&gp[2 * H + n4]);
        float4 e = __ldcs((const float4*)&gp[3 * H + n4]);
        gi.x += a.x; gi.y += a.y; gi.z += a.z; gi.w += a.w;
        gf.x += c.x; gf.y += c.y; gf.z += c.z; gf.w += c.w;
        gg.x += d.x; gg.y += d.y; gg.z += d.z; gg.w += d.w;
        go.x += e.x; go.y += e.y; go.z += e.z; go.w += e.w;
    }
    int idx = b * H + n4;
    float4 cold = *(const float4*)&g_c[idx];
    float hn[4], cn[4];
    float gia[4] = {gi.x, gi.y, gi.z, gi.w};
    float gfa[4] = {gf.x, gf.y, gf.z, gf.w};
    float gga[4] = {gg.x, gg.y, gg.z, gg.w};
    float goa[4] = {go.x, go.y, go.z, go.w};
    float ca[4] = {cold.x, cold.y, cold.z, cold.w};
#pragma unroll
    for (int j = 0; j < 4; j++) {
        float i_ = 1.f / (1.f + expf(-gia[j]));
        float f_ = 1.f / (1.f + expf(-gfa[j]));
        float g_ = tanhf(gga[j]);
        float o_ = 1.f / (1.f + expf(-goa[j]));
        cn[j] = f_ * ca[j] + i_ * g_;
        hn[j] = o_ * tanhf(cn[j]);
    }
    *(float4*)&g_c[idx] = make_float4(cn[0], cn[1], cn[2], cn[3]);
    *(float4*)&g_h[idx] = make_float4(hn[0], hn[1], hn[2], hn[3]);
    uint2 hiP = make_uint2(packbf2(hn[0], hn[1]), packbf2(hn[2], hn[3]));
    uint2 loP = make_uint2(packbf2(lobf(hn[0]), lobf(hn[1])),
                           packbf2(lobf(hn[2]), lobf(hn[3])));
    *(uint2*)&g_h_h[idx] = hiP;                       *(uint2*)&g_h_l[idx] = loP;
    *(uint2*)&g_Arec_h[b * KREC + H + n4] = hiP;      *(uint2*)&g_Arec_l[b * KREC + H + n4] = loP;
    *(uint2*)&g_Aout_h[b * KREC + H + n4] = hiP;      *(uint2*)&g_Aout_l[b * KREC + H + n4] = loP;
}

// ============================================================
// Flash attention split + fused last-block combine/attn/p_gen.
// ============================================================
__global__ __launch_bounds__(256)
void flash_step(int t, const float* __restrict__ enc,
                const float* __restrict__ input_, const float* __restrict__ W_pt,
                const float* __restrict__ b_pt, float* __restrict__ out)
{
    int b = blockIdx.x, sp = blockIdx.y;
    __shared__ float htil[H];
    __shared__ float accS[8][1024];
    __shared__ float wm[8], wl[8], wf[8];
    __shared__ float fP[NSPLIT];
    __shared__ float sM, sL;
    __shared__ int   sLast;
    int tid = threadIdx.x;

    for (int j = tid * 4; j < H; j += 1024) {
        float4 s = make_float4(0.f, 0.f, 0.f, 0.f);
#pragma unroll
        for (int p = 0; p < SK_HTIL; p++) {
            float4 a = __ldcs((const float4*)&g_htil_part[(size_t)p * B * H + b * H + j]);
            s.x += a.x; s.y += a.y; s.z += a.z; s.w += a.w;
        }
        *(float4*)&htil[j] = s;
    }
    __syncthreads();

    int warp = tid >> 5, lane = tid & 31;
    float m = -1e30f, l = 0.f;
    float4 acc[8];
#pragma unroll
    for (int i = 0; i < 8; i++) acc[i] = make_float4(0.f, 0.f, 0.f, 0.f);

    float4 ht[8];
#pragma unroll
    for (int i = 0; i < 8; i++) ht[i] = *(const float4*)&htil[i * 128 + lane * 4];

    const float* encb = enc + (size_t)b * S * H;
    int s0 = sp * 128 + warp * 16;
    for (int si = 0; si < 16; si++) {
        int s = s0 + si;
        const float4* er = (const float4*)(encb + (size_t)s * H) + lane;
        float4 v[8];
#pragma unroll
        for (int i = 0; i < 8; i++) v[i] = __ldcs(er + i * 32);
        float d = 0.f;
#pragma unroll
        for (int i = 0; i < 8; i++)
            d += v[i].x * ht[i].x + v[i].y * ht[i].y + v[i].z * ht[i].z + v[i].w * ht[i].w;
#pragma unroll
        for (int off = 16; off > 0; off >>= 1) d += __shfl_xor_sync(0xffffffffu, d, off);
        if (lane == 0) g_logits[b * S + s] = d;
        float mn = fmaxf(m, d);
        float sc = __expf(m - mn);
        float w  = __expf(d - mn);
        l = l * sc + w;
#pragma unroll
        for (int i = 0; i < 8; i++) {
            acc[i].x = acc[i].x * sc + w * v[i].x;
            acc[i].y = acc[i].y * sc + w * v[i].y;
            acc[i].z = acc[i].z * sc + w * v[i].z;
            acc[i].w = acc[i].w * sc + w * v[i].w;
        }
        m = mn;
    }
#pragma unroll
    for (int i = 0; i < 8; i++) *(float4*)&accS[warp][i * 128 + lane * 4] = acc[i];
    if (lane == 0) { wm[warp] = m; wl[warp] = l; }
    __syncthreads();
    if (tid == 0) {
        float M = -1e30f;
        for (int w0 = 0; w0 < 8; w0++) M = fmaxf(M, wm[w0]);
        float L = 0.f;
        for (int w0 = 0; w0 < 8; w0++) { float f = __expf(wm[w0] - M); wf[w0] = f; L += wl[w0] * f; }
        g_part_m[b * NSPLIT + sp] = M;
        g_part_l[b * NSPLIT + sp] = L;
    }
    __syncthreads();
    for (int j = tid; j < H; j += 256) {
        float s = 0.f;
#pragma unroll
        for (int w0 = 0; w0 < 8; w0++) s += accS[w0][j] * wf[w0];
        g_part_acc[((size_t)b * NSPLIT + sp) * H + j] = s;
    }

    __threadfence();
    __syncthreads();
    if (tid == 0) {
        int old = atomicAdd(&g_cnt[b], 1);
        sLast = (old == NSPLIT - 1);
        if (sLast) { g_cnt[b] = 0; __threadfence(); }
    }
    __syncthreads();
    if (!sLast) return;

    if (tid == 0) {
        float M = -1e30f;
        for (int p = 0; p < NSPLIT; p++) M = fmaxf(M, g_part_m[b * NSPLIT + p]);
        float L = 0.f;
        for (int p = 0; p < NSPLIT; p++) {
            float f = __expf(g_part_m[b * NSPLIT + p] - M);
            fP[p] = f;
            L += g_part_l[b * NSPLIT + p] * f;
        }
        sM = M; sL = L;
    }
    __syncthreads();
    float invL = 1.f / sL;
    for (int j = tid; j < H; j += 256) {
        float ce = 0.f;
#pragma unroll
        for (int p = 0; p < NSPLIT; p++)
            ce += __ldcs(&g_part_acc[((size_t)b * NSPLIT + p) * H + j]) * fP[p];
        float v = ce * invL;
        htil[j] = v;
        split2(v, g_Aout_h[b * KREC + j], g_Aout_l[b * KREC + j]);
    }
    float M = sM;
    for (int s = tid; s < S; s += 256)
        out[OFF_ATTN + (size_t)t * B * S + (size_t)b * S + s] =
            __expf(__ldcs(&g_logits[b * S + s]) - M) * invL;
    __syncthreads();

    const float* xk = input_ + ((size_t)b * T + t) * IN_DIM;
    float s = 0.f;
    for (int k = tid; k < IN_DIM; k += 256) s += W_pt[k] * xk[k];
    for (int k = tid; k < H; k += 256)      s += W_pt[IN_DIM + k] * g_h[b * H + k];
    for (int k = tid; k < H; k += 256)      s += W_pt[IN_DIM + H + k] * htil[k];
    float* red = &accS[0][0];
    red[tid] = s;
    __syncthreads();
    for (int st = 128; st > 0; st >>= 1) {
        if (tid < st) red[tid] += red[tid + st];
        __syncthreads();
    }
    if (tid == 0) {
        float p = 1.f / (1.f + expf(-(red[0] + b_pt[0])));
        out[OFF_P + (size_t)b * T + t] = p;
    }
}

// ============================================================
// ha (float4): reduce wout partials + b_out; write output_/Arec
// ============================================================
__global__ void haepi_step(int t, float* __restrict__ out, const float* __restrict__ b_out)
{
    int v = blockIdx.x * blockDim.x + threadIdx.x;   // B*H/4
    int b = v >> 8;
    int n4 = (v & 255) * 4;
    int idx = b * H + n4;
    float4 s = *(const float4*)&b_out[n4];
#pragma unroll
    for (int p = 0; p < SK_WOUT; p++) {
        float4 a = __ldcs((const float4*)&g_wout_part[(size_t)p * B * H + idx]);
        s.x += a.x; s.y += a.y; s.z += a.z; s.w += a.w;
    }
    *(float4*)&g_Arec[b * KREC + n4] = s;
    uint2 hiP = make_uint2(packbf2(s.x, s.y), packbf2(s.z, s.w));
    uint2 loP = make_uint2(packbf2(lobf(s.x), lobf(s.y)),
                           packbf2(lobf(s.z), lobf(s.w)));
    *(uint2*)&g_Arec_h[b * KREC + n4] = hiP;
    *(uint2*)&g_Arec_l[b * KREC + n4] = loP;
    *(float4*)&out[OFF_OUT + ((size_t)b * T + t) * H + n4] = s;
}

__global__ void final_kernel(const float* __restrict__ past_attn_in,
                             const float* __restrict__ past_dehy_in,
                             float* __restrict__ out)
{
    int idx = blockIdx.x * blockDim.x + threadIdx.x;
    if (idx < B * H) {
        out[OFF_H + idx] = g_h[idx];
        out[OFF_C + idx] = g_c[idx];
        int b = idx >> 10, n = idx & 1023;
        out[OFF_HA + idx] = g_Arec[b * KREC + n];
        out[OFF_DEHY + idx] = past_dehy_in[idx];
    }
    if (idx < B * S) out[OFF_PATTN + idx] = past_attn_in[idx];
    if (idx == 0) out[OFF_LOSS] = 0.f;
}

// ============================================================
extern "C" void kernel_launch(void* const* d_in, const int* in_sizes, int n_in,
                              void* d_out, int out_size)
{
    int base = (in_sizes[0] == 1) ? 1 : 0;
    const float* input_    = (const float*)d_in[base + 0];
    const float* hidden_h  = (const float*)d_in[base + 1];
    const float* hidden_c  = (const float*)d_in[base + 2];
    const float* h_attn    = (const float*)d_in[base + 3];
    const float* enc       = (const float*)d_in[base + 4];
    const float* past_attn = (const float*)d_in[base + 5];
    const float* past_dehy = (const float*)d_in[base + 7];
    const float* W_ih  = (const float*)d_in[base + 8];
    const float* b_ih  = (const float*)d_in[base + 9];
    const float* W_hh  = (const float*)d_in[base + 10];
    const float* b_hh  = (const float*)d_in[base + 11];
    const float* W_attn= (const float*)d_in[base + 12];
    const float* W_out = (const float*)d_in[base + 13];
    const float* b_out = (const float*)d_in[base + 14];
    const float* W_pt  = (const float*)d_in[base + 15];
    const float* b_pt  = (const float*)d_in[base + 16];
    float* out = (float*)d_out;

    float *pXg, *pbg, *pGates, *pHtil, *pWoutp;
    __nv_bfloat16 *pWrh, *pWrl, *pWath, *pWatl, *pWouth, *pWoutl, *pWihh, *pWihl;
    __nv_bfloat16 *pInh, *pInl, *pArech, *pArecl, *pAouth, *pAoutl, *pHh, *pHl;
    cudaGetSymbolAddress((void**)&pXg,    g_Xg);
    cudaGetSymbolAddress((void**)&pbg,    g_biasg);
    cudaGetSymbolAddress((void**)&pGates, g_gates_part);
    cudaGetSymbolAddress((void**)&pHtil,  g_htil_part);
    cudaGetSymbolAddress((void**)&pWoutp, g_wout_part);
    cudaGetSymbolAddress((void**)&pWrh,   g_Wr_h);
    cudaGetSymbolAddress((void**)&pWrl,   g_Wr_l);
    cudaGetSymbolAddress((void**)&pWath,  g_Wat_h);
    cudaGetSymbolAddress((void**)&pWatl,  g_Wat_l);
    cudaGetSymbolAddress((void**)&pWouth, g_Wout_h);
    cudaGetSymbolAddress((void**)&pWoutl, g_Wout_l);
    cudaGetSymbolAddress((void**)&pWihh,  g_Wih_h);
    cudaGetSymbolAddress((void**)&pWihl,  g_Wih_l);
    cudaGetSymbolAddress((void**)&pInh,   g_in_h);
    cudaGetSymbolAddress((void**)&pInl,   g_in_l);
    cudaGetSymbolAddress((void**)&pArech, g_Arec_h);
    cudaGetSymbolAddress((void**)&pArecl, g_Arec_l);
    cudaGetSymbolAddress((void**)&pAouth, g_Aout_h);
    cudaGetSymbolAddress((void**)&pAoutl, g_Aout_l);
    cudaGetSymbolAddress((void**)&pHh,    g_h_h);
    cudaGetSymbolAddress((void**)&pHl,    g_h_l);

    static bool attr_set = false;
    if (!attr_set) {
        cudaFuncSetAttribute((const void*)hgemm_tn<64, 3>,
                             cudaFuncAttributeMaxDynamicSharedMemorySize, SMEM64);
        attr_set = true;
    }

    prep_kernel<<<2048, 256>>>(W_ih, W_hh, b_ih, b_hh, W_attn, W_out, input_);
    init_kernel<<<(B * H + 255) / 256, 256>>>(hidden_h, hidden_c, h_attn);

    // Xg = input_ @ W_ih[:, :IN].T + (b_ih + b_hh)  (BM=64, 2 blk/SM)
    hgemm_tn<64, 3><<<dim3(G4 / 128, (B * T) / 64, 1), 256, SMEM64>>>(
        pInh, pInl, IN_DIM, pWihh, pWihl, IN_DIM, pXg, B * T, G4, IN_DIM, pbg);

    for (int t = 0; t < T; t++) {
        // gates partial: [ha, h] @ [W_ih[:,IN:], W_hh].T  (BM=64, 2 blk/SM)
        hgemm_tn<64, 3><<<dim3(G4 / 128, 2, SK_GATES), 256, SMEM64>>>(
            pArech, pArecl, KREC, pWrh, pWrl, KREC, pGates, B, G4,
            KREC / SK_GATES, nullptr);
        lstm_step<<<(B * H / 4) / 256, 256>>>(t);
        // h~ = h @ W_attn
        hgemm_tn<64, 3><<<dim3(H / 128, 2, SK_HTIL), 256, SMEM64>>>(
            pHh, pHl, H, pWath, pWatl, H, pHtil, B, H, H / SK_HTIL, nullptr);
        flash_step<<<dim3(B, NSPLIT), 256>>>(t, enc, input_, W_pt, b_pt, out);
        // ha partial: [c_enc, h] @ W_out.T
        hgemm_tn<64, 3><<<dim3(H / 128, 2, SK_WOUT), 256, SMEM64>>>(
            pAouth, pAoutl, KREC, pWouth, pWoutl, KREC, pWoutp, B, H,
            KREC / SK_WOUT, nullptr);
        haepi_step<<<(B * H / 4) / 256, 256>>>(t, out, b_out);
    }
    final_kernel<<<(B * H + 255) / 256, 256>>>(past_attn, past_dehy, out);
}

// round 17
// speedup vs baseline: 1.0456x; 1.0295x over previous
#include <cuda_runtime.h>
#include <cuda_bf16.h>
#include <math.h>

#define B 128
#define T 32
#define S 512
#define H 1024
#define IN_DIM 1024
#define G4 4096          // 4*H
#define KREC 2048        // H (ha) + H (h)

#define SK_GATES 4
#define SK_HTIL 8
#define SK_WOUT 8
#define NSPLIT 4

// ---- output offsets (flattened tuple, fp32) ----
#define OFF_OUT   0ull
#define OFF_H     4194304ull
#define OFF_C     4325376ull
#define OFF_HA    4456448ull
#define OFF_ATTN  4587520ull
#define OFF_PATTN 6684672ull
#define OFF_P     6750208ull
#define OFF_DEHY  6754304ull
#define OFF_LOSS  6885376ull

// ---- scratch ----
__device__ float g_Xg[(size_t)B * T * G4];        // rows (b*T + t)
__device__ float g_biasg[G4];
__device__ float g_gates_part[SK_GATES * B * G4];
__device__ float g_htil_part[SK_HTIL * B * H];
__device__ float g_wout_part[SK_WOUT * B * H];
__device__ float g_Arec[B * KREC];                // fp32 ha (final output)
__device__ float g_h[B * H];
__device__ float g_c[B * H];
__device__ float g_logits[B * S];
__device__ float g_part_acc[B * NSPLIT * H];
__device__ float g_part_m[B * NSPLIT];
__device__ float g_part_l[B * NSPLIT];
__device__ int   g_cnt[B];                        // zero-init; self-resetting

// bf16 hi/lo split weights (built once in prep)
__device__ __nv_bfloat16 g_Wr_h[(size_t)G4 * KREC];
__device__ __nv_bfloat16 g_Wr_l[(size_t)G4 * KREC];
__device__ __nv_bfloat16 g_Wat_h[H * H];
__device__ __nv_bfloat16 g_Wat_l[H * H];
__device__ __nv_bfloat16 g_Wout_h[H * KREC];
__device__ __nv_bfloat16 g_Wout_l[H * KREC];
__device__ __nv_bfloat16 g_Wih_h[(size_t)G4 * IN_DIM];
__device__ __nv_bfloat16 g_Wih_l[(size_t)G4 * IN_DIM];
__device__ __nv_bfloat16 g_in_h[(size_t)B * T * IN_DIM];
__device__ __nv_bfloat16 g_in_l[(size_t)B * T * IN_DIM];
// bf16 hi/lo activations
__device__ __nv_bfloat16 g_Arec_h[B * KREC];
__device__ __nv_bfloat16 g_Arec_l[B * KREC];
__device__ __nv_bfloat16 g_Aout_h[B * KREC];
__device__ __nv_bfloat16 g_Aout_l[B * KREC];
__device__ __nv_bfloat16 g_h_h[B * H];
__device__ __nv_bfloat16 g_h_l[B * H];

__device__ __forceinline__ void split2(float x, __nv_bfloat16& hi, __nv_bfloat16& lo)
{
    hi = __float2bfloat16(x);
    lo = __float2bfloat16(x - __bfloat162float(hi));
}
__device__ __forceinline__ unsigned packbf2(float a, float b)
{
    __nv_bfloat162 t = __floats2bfloat162_rn(a, b);
    return *(unsigned*)&t;
}
__device__ __forceinline__ float lobf(float x)
{
    return x - __bfloat162float(__float2bfloat16(x));
}

// ============================================================
// Tensor-core GEMM: C = A @ W.T with bf16x3 split.
// BM=128/NST=4 (1 blk/SM) for big-M; BM=64/NST=3 (2 blk/SM) else.
// ============================================================
#define SKP  40
#define TILE (128 * SKP)

__device__ __forceinline__ void ldsm4(unsigned* r, unsigned addr)
{
    asm volatile("ldmatrix.sync.aligned.m8n8.x4.shared.b16 {%0,%1,%2,%3}, [%4];"
                 : "=r"(r[0]), "=r"(r[1]), "=r"(r[2]), "=r"(r[3]) : "r"(addr));
}
__device__ __forceinline__ void mma16816(float* d, const unsigned* a, const unsigned* b)
{
    asm volatile("mma.sync.aligned.m16n8k16.row.col.f32.bf16.bf16.f32 "
                 "{%0,%1,%2,%3}, {%4,%5,%6,%7}, {%8,%9}, {%0,%1,%2,%3};"
                 : "+f"(d[0]), "+f"(d[1]), "+f"(d[2]), "+f"(d[3])
                 : "r"(a[0]), "r"(a[1]), "r"(a[2]), "r"(a[3]), "r"(b[0]), "r"(b[1]));
}
#define CP16(dst, src) \
    asm volatile("cp.async.cg.shared.global [%0], [%1], 16;" :: "r"(dst), "l"(src))
#define CP_COMMIT() asm volatile("cp.async.commit_group;")
#define CP_WAIT(n)  asm volatile("cp.async.wait_group %0;" :: "n"(n))

template <int BM, int NST>
__global__ __launch_bounds__(256, (BM == 64) ? 2 : 1)
void hgemm_tn(const __nv_bfloat16* __restrict__ Ah, const __nv_bfloat16* __restrict__ Al,
              int lda,
              const __nv_bfloat16* __restrict__ Wh, const __nv_bfloat16* __restrict__ Wl,
              int ldw,
              float* __restrict__ Cpart, int M, int N, int Kslice,
              const float* __restrict__ bias)
{
    constexpr int ATILE = BM * SKP;             // A tile elems (one component)
    constexpr int STAGE = 2 * ATILE + 2 * TILE; // elems per stage
    constexpr int MT = BM / 32;                 // m-tiles per warp

    extern __shared__ __nv_bfloat16 smem[];
    const int bn = blockIdx.x, bm = blockIdx.y, bz = blockIdx.z;
    Ah += (size_t)bm * BM * lda + (size_t)bz * Kslice;
    Al += (size_t)bm * BM * lda + (size_t)bz * Kslice;
    Wh += (size_t)bn * 128 * ldw + (size_t)bz * Kslice;
    Wl += (size_t)bn * 128 * ldw + (size_t)bz * Kslice;
    float* C = Cpart + (size_t)bz * M * N + (size_t)bm * BM * N + (size_t)bn * 128;

    const int tid = threadIdx.x;
    const int warp = tid >> 5, lane = tid & 31;
    const int wm = (warp >> 2) * (BM / 2);
    const int wn = (warp & 3) * 32;

    const unsigned sbase = (unsigned)__cvta_generic_to_shared(smem);

    float acc[MT][4][4];
#pragma unroll
    for (int i = 0; i < MT; i++)
#pragma unroll
        for (int j = 0; j < 4; j++)
#pragma unroll
            for (int q = 0; q < 4; q++) acc[i][j][q] = 0.f;

    const int nIter = Kslice >> 5;

    auto load_stage = [&](int stage, int ko) {
        unsigned sb = sbase + (unsigned)(stage * STAGE) * 2;
#pragma unroll
        for (int i = 0; i < BM / 64; i++) {
            int idx = i * 256 + tid;
            int row = idx >> 2, ch = (idx & 3) * 8;
            unsigned doff = (unsigned)(row * SKP + ch) * 2;
            size_t ga = (size_t)row * lda + ko + ch;
            CP16(sb + doff,                          Ah + ga);
            CP16(sb + (unsigned)ATILE * 2 + doff,    Al + ga);
        }
#pragma unroll
        for (int i = 0; i < 2; i++) {
            int idx = i * 256 + tid;
            int row = idx >> 2, ch = (idx & 3) * 8;
            unsigned doff = (unsigned)(row * SKP + ch) * 2;
            size_t gw = (size_t)row * ldw + ko + ch;
            CP16(sb + (unsigned)(2 * ATILE) * 2 + doff,        Wh + gw);
            CP16(sb + (unsigned)(2 * ATILE + TILE) * 2 + doff, Wl + gw);
        }
    };

    for (int s = 0; s < NST - 1 && s < nIter; s++) {
        load_stage(s, s * 32);
        CP_COMMIT();
    }

    const int rA = lane & 15;
    const int kA = (lane >> 4) * 8;
    const int rB = (lane & 7) + ((lane & 16) ? 8 : 0);
    const int kB = (lane & 8);

    int sIdx = 0, tIdx = NST - 1;
    for (int it = 0; it < nIter; it++) {
        if (it + NST - 1 <= nIter) { CP_WAIT(NST - 2); } else { CP_WAIT(0); }
        __syncthreads();

        unsigned base = sbase + (unsigned)(sIdx * STAGE) * 2;
#pragma unroll
        for (int k16 = 0; k16 < 32; k16 += 16) {
            unsigned ah[MT][4], al[MT][4], bh[4][2], bl[4][2];
#pragma unroll
            for (int mt = 0; mt < MT; mt++) {
                unsigned ad = base + (unsigned)((wm + mt * 16 + rA) * SKP + k16 + kA) * 2;
                ldsm4(ah[mt], ad);
                ldsm4(al[mt], ad + (unsigned)ATILE * 2);
            }
#pragma unroll
            for (int np = 0; np < 2; np++) {
                unsigned bd = base + (unsigned)(2 * ATILE) * 2 +
                              (unsigned)((wn + np * 16 + rB) * SKP + k16 + kB) * 2;
                unsigned r[4];
                ldsm4(r, bd);
                bh[np * 2][0] = r[0]; bh[np * 2][1] = r[1];
                bh[np * 2 + 1][0] = r[2]; bh[np * 2 + 1][1] = r[3];
                ldsm4(r, bd + (unsigned)TILE * 2);
                bl[np * 2][0] = r[0]; bl[np * 2][1] = r[1];
                bl[np * 2 + 1][0] = r[2]; bl[np * 2 + 1][1] = r[3];
            }
#pragma unroll
            for (int mt = 0; mt < MT; mt++)
#pragma unroll
                for (int nt = 0; nt < 4; nt++) {
                    mma16816(acc[mt][nt], ah[mt], bh[nt]);
                    mma16816(acc[mt][nt], al[mt], bh[nt]);
                    mma16816(acc[mt][nt], ah[mt], bl[nt]);
                }
        }
        if (it + NST - 1 < nIter) {
            load_stage(tIdx, (it + NST - 1) * 32);
            CP_COMMIT();
        }
        sIdx = (sIdx + 1 == NST) ? 0 : sIdx + 1;
        tIdx = (tIdx + 1 == NST) ? 0 : tIdx + 1;
    }

    const int er = lane >> 2;
    const int ec = (lane & 3) * 2;
#pragma unroll
    for (int mt = 0; mt < MT; mt++)
#pragma unroll
        for (int nt = 0; nt < 4; nt++) {
            int r0 = wm + mt * 16 + er;
            int c0 = wn + nt * 8 + ec;
            float b0 = 0.f, b1 = 0.f;
            if (bias != nullptr) {
                b0 = bias[bn * 128 + c0];
                b1 = bias[bn * 128 + c0 + 1];
            }
            float* p0 = C + (size_t)r0 * N + c0;
            float* p1 = C + (size_t)(r0 + 8) * N + c0;
            p0[0] = acc[mt][nt][0] + b0;
            p0[1] = acc[mt][nt][1] + b1;
            p1[0] = acc[mt][nt][2] + b0;
            p1[1] = acc[mt][nt][3] + b1;
        }
}

#define SMEM64  (3 * (2 * 64 * SKP + 2 * TILE) * 2)
#define SMEM128 (4 * (2 * 128 * SKP + 2 * TILE) * 2)

// ============================================================
// Setup kernels
// ============================================================
__global__ void prep_kernel(const float* __restrict__ W_ih, const float* __restrict__ W_hh,
                            const float* __restrict__ b_ih, const float* __restrict__ b_hh,
                            const float* __restrict__ W_attn, const float* __restrict__ W_out,
                            const float* __restrict__ input_)
{
    size_t stride = (size_t)gridDim.x * blockDim.x;
    size_t start = (size_t)blockIdx.x * blockDim.x + threadIdx.x;
    for (size_t idx = start; idx < (size_t)G4 * KREC; idx += stride) {
        int n = (int)(idx >> 11);
        int k = (int)(idx & 2047);
        float v = (k < H) ? W_ih[(size_t)n * KREC + IN_DIM + k]
                          : W_hh[(size_t)n * H + (k - H)];
        split2(v, g_Wr_h[idx], g_Wr_l[idx]);
    }
    for (size_t idx = start; idx < (size_t)H * H; idx += stride) {
        int n = (int)(idx >> 10), k = (int)(idx & 1023);
        split2(W_attn[(size_t)k * H + n], g_Wat_h[idx], g_Wat_l[idx]);
    }
    for (size_t idx = start; idx < (size_t)H * KREC; idx += stride)
        split2(W_out[idx], g_Wout_h[idx], g_Wout_l[idx]);
    for (size_t idx = start; idx < (size_t)G4 * IN_DIM; idx += stride) {
        int n = (int)(idx >> 10), k = (int)(idx & 1023);
        split2(W_ih[(size_t)n * KREC + k], g_Wih_h[idx], g_Wih_l[idx]);
    }
    for (size_t idx = start; idx < (size_t)B * T * IN_DIM; idx += stride)
        split2(input_[idx], g_in_h[idx], g_in_l[idx]);
    for (size_t idx = start; idx < (size_t)G4; idx += stride)
        g_biasg[idx] = b_ih[idx] + b_hh[idx];
}

__global__ void init_kernel(const float* __restrict__ hh, const float* __restrict__ hc,
                            const float* __restrict__ ha)
{
    int idx = blockIdx.x * blockDim.x + threadIdx.x;
    if (idx < B * H) {
        int b = idx >> 10, n = idx & 1023;
        g_h[idx] = hh[idx];
        g_c[idx] = hc[idx];
        split2(ha[idx], g_Arec_h[b * KREC + n], g_Arec_l[b * KREC + n]);
        split2(hh[idx], g_Arec_h[b * KREC + H + n], g_Arec_l[b * KREC + H + n]);
        if (idx < B) g_cnt[idx] = 0;
    }
}

// ============================================================
// LSTM cell (float4): reduce gate partials + Xg, update h/c
// ============================================================
__global__ void lstm_step(int t)
{
    int v = blockIdx.x * blockDim.x + threadIdx.x;   // B*H/4
    int b = v >> 8;
    int n4 = (v & 255) * 4;
    size_t row = ((size_t)b * T + t) * G4;
    float4 gi = __ldcs((const float4*)&g_Xg[row + n4]);
    float4 gf = __ldcs((const float4*)&g_Xg[row + H + n4]);
    float4 gg = __ldcs((const float4*)&g_Xg[row + 2 * H + n4]);
    float4 go = __ldcs((const float4*)&g_Xg[row + 3 * H + n4]);
#pragma unroll
    for (int p = 0; p < SK_GATES; p++) {
        const float* gp = g_gates_part + (size_t)p * B * G4 + (size_t)b * G4;
        float4 a = __ldcs((const float4*)&gp[n4]);
        float4 c = __ldcs((const float4*)&gp[H + n4]);
        float4 d = __ldcs((const float4*)&gp[2 * H + n4]);
        float4 e = __ldcs((const float4*)&gp[3 * H + n4]);
        gi.x += a.x; gi.y += a.y; gi.z += a.z; gi.w += a.w;
        gf.x += c.x; gf.y += c.y; gf.z += c.z; gf.w += c.w;
        gg.x += d.x; gg.y += d.y; gg.z += d.z; gg.w += d.w;
        go.x += e.x; go.y += e.y; go.z += e.z; go.w += e.w;
    }
    int idx = b * H + n4;
    float4 cold = *(const float4*)&g_c[idx];
    float hn[4], cn[4];
    float gia[4] = {gi.x, gi.y, gi.z, gi.w};
    float gfa[4] = {gf.x, gf.y, gf.z, gf.w};
    float gga[4] = {gg.x, gg.y, gg.z, gg.w};
    float goa[4] = {go.x, go.y, go.z, go.w};
    float ca[4] = {cold.x, cold.y, cold.z, cold.w};
#pragma unroll
    for (int j = 0; j < 4; j++) {
        float i_ = 1.f / (1.f + expf(-gia[j]));
        float f_ = 1.f / (1.f + expf(-gfa[j]));
        float g_ = tanhf(gga[j]);
        float o_ = 1.f / (1.f + expf(-goa[j]));
        cn[j] = f_ * ca[j] + i_ * g_;
        hn[j] = o_ * tanhf(cn[j]);
    }
    *(float4*)&g_c[idx] = make_float4(cn[0], cn[1], cn[2], cn[3]);
    *(float4*)&g_h[idx] = make_float4(hn[0], hn[1], hn[2], hn[3]);
    uint2 hiP = make_uint2(packbf2(hn[0], hn[1]), packbf2(hn[2], hn[3]));
    uint2 loP = make_uint2(packbf2(lobf(hn[0]), lobf(hn[1])),
                           packbf2(lobf(hn[2]), lobf(hn[3])));
    *(uint2*)&g_h_h[idx] = hiP;                       *(uint2*)&g_h_l[idx] = loP;
    *(uint2*)&g_Arec_h[b * KREC + H + n4] = hiP;      *(uint2*)&g_Arec_l[b * KREC + H + n4] = loP;
    *(uint2*)&g_Aout_h[b * KREC + H + n4] = hiP;      *(uint2*)&g_Aout_l[b * KREC + H + n4] = loP;
}

// ============================================================
// Flash attention split + fused last-block combine/attn/p_gen.
// ============================================================
__global__ __launch_bounds__(256)
void flash_step(int t, const float* __restrict__ enc,
                const float* __restrict__ input_, const float* __restrict__ W_pt,
                const float* __restrict__ b_pt, float* __restrict__ out)
{
    int b = blockIdx.x, sp = blockIdx.y;
    __shared__ float htil[H];
    __shared__ float accS[8][1024];
    __shared__ float wm[8], wl[8], wf[8];
    __shared__ float fP[NSPLIT];
    __shared__ float sM, sL;
    __shared__ int   sLast;
    int tid = threadIdx.x;

    for (int j = tid * 4; j < H; j += 1024) {
        float4 s = make_float4(0.f, 0.f, 0.f, 0.f);
#pragma unroll
        for (int p = 0; p < SK_HTIL; p++) {
            float4 a = __ldcs((const float4*)&g_htil_part[(size_t)p * B * H + b * H + j]);
            s.x += a.x; s.y += a.y; s.z += a.z; s.w += a.w;
        }
        *(float4*)&htil[j] = s;
    }
    __syncthreads();

    int warp = tid >> 5, lane = tid & 31;
    float m = -1e30f, l = 0.f;
    float4 acc[8];
#pragma unroll
    for (int i = 0; i < 8; i++) acc[i] = make_float4(0.f, 0.f, 0.f, 0.f);

    float4 ht[8];
#pragma unroll
    for (int i = 0; i < 8; i++) ht[i] = *(const float4*)&htil[i * 128 + lane * 4];

    const float* encb = enc + (size_t)b * S * H;
    int s0 = sp * 128 + warp * 16;
    for (int si = 0; si < 16; si++) {
        int s = s0 + si;
        const float4* er = (const float4*)(encb + (size_t)s * H) + lane;
        float4 v[8];
#pragma unroll
        for (int i = 0; i < 8; i++) v[i] = __ldcs(er + i * 32);
        float d = 0.f;
#pragma unroll
        for (int i = 0; i < 8; i++)
            d += v[i].x * ht[i].x + v[i].y * ht[i].y + v[i].z * ht[i].z + v[i].w * ht[i].w;
#pragma unroll
        for (int off = 16; off > 0; off >>= 1) d += __shfl_xor_sync(0xffffffffu, d, off);
        if (lane == 0) g_logits[b * S + s] = d;
        float mn = fmaxf(m, d);
        float sc = __expf(m - mn);
        float w  = __expf(d - mn);
        l = l * sc + w;
#pragma unroll
        for (int i = 0; i < 8; i++) {
            acc[i].x = acc[i].x * sc + w * v[i].x;
            acc[i].y = acc[i].y * sc + w * v[i].y;
            acc[i].z = acc[i].z * sc + w * v[i].z;
            acc[i].w = acc[i].w * sc + w * v[i].w;
        }
        m = mn;
    }
#pragma unroll
    for (int i = 0; i < 8; i++) *(float4*)&accS[warp][i * 128 + lane * 4] = acc[i];
    if (lane == 0) { wm[warp] = m; wl[warp] = l; }
    __syncthreads();
    if (tid == 0) {
        float M = -1e30f;
        for (int w0 = 0; w0 < 8; w0++) M = fmaxf(M, wm[w0]);
        float L = 0.f;
        for (int w0 = 0; w0 < 8; w0++) { float f = __expf(wm[w0] - M); wf[w0] = f; L += wl[w0] * f; }
        g_part_m[b * NSPLIT + sp] = M;
        g_part_l[b * NSPLIT + sp] = L;
    }
    __syncthreads();
    for (int j = tid; j < H; j += 256) {
        float s = 0.f;
#pragma unroll
        for (int w0 = 0; w0 < 8; w0++) s += accS[w0][j] * wf[w0];
        g_part_acc[((size_t)b * NSPLIT + sp) * H + j] = s;
    }

    __threadfence();
    __syncthreads();
    if (tid == 0) {
        int old = atomicAdd(&g_cnt[b], 1);
        sLast = (old == NSPLIT - 1);
        if (sLast) { g_cnt[b] = 0; __threadfence(); }
    }
    __syncthreads();
    if (!sLast) return;

    if (tid == 0) {
        float M = -1e30f;
        for (int p = 0; p < NSPLIT; p++) M = fmaxf(M, g_part_m[b * NSPLIT + p]);
        float L = 0.f;
        for (int p = 0; p < NSPLIT; p++) {
            float f = __expf(g_part_m[b * NSPLIT + p] - M);
            fP[p] = f;
            L += g_part_l[b * NSPLIT + p] * f;
        }
        sM = M; sL = L;
    }
    __syncthreads();
    float invL = 1.f / sL;
    for (int j = tid; j < H; j += 256) {
        float ce = 0.f;
#pragma unroll
        for (int p = 0; p < NSPLIT; p++)
            ce += __ldcs(&g_part_acc[((size_t)b * NSPLIT + p) * H + j]) * fP[p];
        float v = ce * invL;
        htil[j] = v;
        split2(v, g_Aout_h[b * KREC + j], g_Aout_l[b * KREC + j]);
    }
    float M = sM;
    for (int s = tid; s < S; s += 256)
        out[OFF_ATTN + (size_t)t * B * S + (size_t)b * S + s] =
            __expf(__ldcs(&g_logits[b * S + s]) - M) * invL;
    __syncthreads();

    const float* xk = input_ + ((size_t)b * T + t) * IN_DIM;
    float s = 0.f;
    for (int k = tid; k < IN_DIM; k += 256) s += W_pt[k] * xk[k];
    for (int k = tid; k < H; k += 256)      s += W_pt[IN_DIM + k] * g_h[b * H + k];
    for (int k = tid; k < H; k += 256)      s += W_pt[IN_DIM + H + k] * htil[k];
    float* red = &accS[0][0];
    red[tid] = s;
    __syncthreads();
    for (int st = 128; st > 0; st >>= 1) {
        if (tid < st) red[tid] += red[tid + st];
        __syncthreads();
    }
    if (tid == 0) {
        float p = 1.f / (1.f + expf(-(red[0] + b_pt[0])));
        out[OFF_P + (size_t)b * T + t] = p;
    }
}

// ============================================================
// ha (float4): reduce wout partials + b_out; write output_/Arec
// ============================================================
__global__ void haepi_step(int t, float* __restrict__ out, const float* __restrict__ b_out)
{
    int v = blockIdx.x * blockDim.x + threadIdx.x;   // B*H/4
    int b = v >> 8;
    int n4 = (v & 255) * 4;
    int idx = b * H + n4;
    float4 s = *(const float4*)&b_out[n4];
#pragma unroll
    for (int p = 0; p < SK_WOUT; p++) {
        float4 a = __ldcs((const float4*)&g_wout_part[(size_t)p * B * H + idx]);
        s.x += a.x; s.y += a.y; s.z += a.z; s.w += a.w;
    }
    *(float4*)&g_Arec[b * KREC + n4] = s;
    uint2 hiP = make_uint2(packbf2(s.x, s.y), packbf2(s.z, s.w));
    uint2 loP = make_uint2(packbf2(lobf(s.x), lobf(s.y)),
                           packbf2(lobf(s.z), lobf(s.w)));
    *(uint2*)&g_Arec_h[b * KREC + n4] = hiP;
    *(uint2*)&g_Arec_l[b * KREC + n4] = loP;
    *(float4*)&out[OFF_OUT + ((size_t)b * T + t) * H + n4] = s;
}

__global__ void final_kernel(const float* __restrict__ past_attn_in,
                             const float* __restrict__ past_dehy_in,
                             float* __restrict__ out)
{
    int idx = blockIdx.x * blockDim.x + threadIdx.x;
    if (idx < B * H) {
        out[OFF_H + idx] = g_h[idx];
        out[OFF_C + idx] = g_c[idx];
        int b = idx >> 10, n = idx & 1023;
        out[OFF_HA + idx] = g_Arec[b * KREC + n];
        out[OFF_DEHY + idx] = past_dehy_in[idx];
    }
    if (idx < B * S) out[OFF_PATTN + idx] = past_attn_in[idx];
    if (idx == 0) out[OFF_LOSS] = 0.f;
}

// ============================================================
extern "C" void kernel_launch(void* const* d_in, const int* in_sizes, int n_in,
                              void* d_out, int out_size)
{
    int base = (in_sizes[0] == 1) ? 1 : 0;
    const float* input_    = (const float*)d_in[base + 0];
    const float* hidden_h  = (const float*)d_in[base + 1];
    const float* hidden_c  = (const float*)d_in[base + 2];
    const float* h_attn    = (const float*)d_in[base + 3];
    const float* enc       = (const float*)d_in[base + 4];
    const float* past_attn = (const float*)d_in[base + 5];
    const float* past_dehy = (const float*)d_in[base + 7];
    const float* W_ih  = (const float*)d_in[base + 8];
    const float* b_ih  = (const float*)d_in[base + 9];
    const float* W_hh  = (const float*)d_in[base + 10];
    const float* b_hh  = (const float*)d_in[base + 11];
    const float* W_attn= (const float*)d_in[base + 12];
    const float* W_out = (const float*)d_in[base + 13];
    const float* b_out = (const float*)d_in[base + 14];
    const float* W_pt  = (const float*)d_in[base + 15];
    const float* b_pt  = (const float*)d_in[base + 16];
    float* out = (float*)d_out;

    float *pXg, *pbg, *pGates, *pHtil, *pWoutp;
    __nv_bfloat16 *pWrh, *pWrl, *pWath, *pWatl, *pWouth, *pWoutl, *pWihh, *pWihl;
    __nv_bfloat16 *pInh, *pInl, *pArech, *pArecl, *pAouth, *pAoutl, *pHh, *pHl;
    cudaGetSymbolAddress((void**)&pXg,    g_Xg);
    cudaGetSymbolAddress((void**)&pbg,    g_biasg);
    cudaGetSymbolAddress((void**)&pGates, g_gates_part);
    cudaGetSymbolAddress((void**)&pHtil,  g_htil_part);
    cudaGetSymbolAddress((void**)&pWoutp, g_wout_part);
    cudaGetSymbolAddress((void**)&pWrh,   g_Wr_h);
    cudaGetSymbolAddress((void**)&pWrl,   g_Wr_l);
    cudaGetSymbolAddress((void**)&pWath,  g_Wat_h);
    cudaGetSymbolAddress((void**)&pWatl,  g_Wat_l);
    cudaGetSymbolAddress((void**)&pWouth, g_Wout_h);
    cudaGetSymbolAddress((void**)&pWoutl, g_Wout_l);
    cudaGetSymbolAddress((void**)&pWihh,  g_Wih_h);
    cudaGetSymbolAddress((void**)&pWihl,  g_Wih_l);
    cudaGetSymbolAddress((void**)&pInh,   g_in_h);
    cudaGetSymbolAddress((void**)&pInl,   g_in_l);
    cudaGetSymbolAddress((void**)&pArech, g_Arec_h);
    cudaGetSymbolAddress((void**)&pArecl, g_Arec_l);
    cudaGetSymbolAddress((void**)&pAouth, g_Aout_h);
    cudaGetSymbolAddress((void**)&pAoutl, g_Aout_l);
    cudaGetSymbolAddress((void**)&pHh,    g_h_h);
    cudaGetSymbolAddress((void**)&pHl,    g_h_l);

    static bool attr_set = false;
    if (!attr_set) {
        cudaFuncSetAttribute((const void*)hgemm_tn<128, 4>,
                             cudaFuncAttributeMaxDynamicSharedMemorySize, SMEM128);
        cudaFuncSetAttribute((const void*)hgemm_tn<64, 3>,
                             cudaFuncAttributeMaxDynamicSharedMemorySize, SMEM64);
        attr_set = true;
    }

    prep_kernel<<<2048, 256>>>(W_ih, W_hh, b_ih, b_hh, W_attn, W_out, input_);
    init_kernel<<<(B * H + 255) / 256, 256>>>(hidden_h, hidden_c, h_attn);

    // Xg = input_ @ W_ih[:, :IN].T + (b_ih + b_hh)  (BM=128, best measured)
    hgemm_tn<128, 4><<<dim3(G4 / 128, (B * T) / 128, 1), 256, SMEM128>>>(
        pInh, pInl, IN_DIM, pWihh, pWihl, IN_DIM, pXg, B * T, G4, IN_DIM, pbg);

    for (int t = 0; t < T; t++) {
        // gates partial: [ha, h] @ [W_ih[:,IN:], W_hh].T  (BM=64, 2 blk/SM)
        hgemm_tn<64, 3><<<dim3(G4 / 128, 2, SK_GATES), 256, SMEM64>>>(
            pArech, pArecl, KREC, pWrh, pWrl, KREC, pGates, B, G4,
            KREC / SK_GATES, nullptr);
        lstm_step<<<(B * H / 4) / 256, 256>>>(t);
        // h~ = h @ W_attn
        hgemm_tn<64, 3><<<dim3(H / 128, 2, SK_HTIL), 256, SMEM64>>>(
            pHh, pHl, H, pWath, pWatl, H, pHtil, B, H, H / SK_HTIL, nullptr);
        flash_step<<<dim3(B, NSPLIT), 256>>>(t, enc, input_, W_pt, b_pt, out);
        // ha partial: [c_enc, h] @ W_out.T
        hgemm_tn<64, 3><<<dim3(H / 128, 2, SK_WOUT), 256, SMEM64>>>(
            pAouth, pAoutl, KREC, pWouth, pWoutl, KREC, pWoutp, B, H,
            KREC / SK_WOUT, nullptr);
        haepi_step<<<(B * H / 4) / 256, 256>>>(t, out, b_out);
    }
    final_kernel<<<(B * H + 255) / 256, 256>>>(past_attn, past_dehy, out);
}